// round 14
// baseline (speedup 1.0000x reference)
#include <cuda_runtime.h>
#include <cuda_fp16.h>
#include <math.h>
#include <cstdint>

// ===========================================================================
// Problem constants
// ===========================================================================
#define T_TOK   4096
#define H_DIM   1024
#define I_DIM   1408
#define E_NUM   8
#define N_ASG   (T_TOK * 2)
#define NK1     16                  // H_DIM/64 tiles (gemm1 K)
#define NK2     22                  // I_DIM/64 tiles (gemm2 K)

// Tiling: CTA 128x128, 4 warps = 2(m) x 2(n), warp tile 64x64, 128 threads
#define BM      128
#define BN      128
#define TILEB   16384               // 128 rows x 128B (64 fp16 k-values)
#define STAGEB  (2 * TILEB)         // A + B = 32768
#define SMEM_BYTES (2 * STAGEB)     // 65536 -> 2 CTAs/SM

// Plain fp16 gmem, row-major K-contiguous: (row, k64-slab) -> 128B block
__device__ __align__(128) unsigned char xbuf[(size_t)T_TOK * NK1 * 128];
__device__ __align__(128) unsigned char w1buf[(size_t)E_NUM * 2816 * NK1 * 128];
__device__ __align__(128) unsigned char w2buf[(size_t)E_NUM * 1024 * NK2 * 128];
__device__ __align__(128) unsigned char hbuf[(size_t)N_ASG * NK2 * 128];
__device__ float d_yslot[(size_t)N_ASG * H_DIM];
__device__ int   d_asg[E_NUM * T_TOK];
__device__ float d_topw[N_ASG];
__device__ int   d_topi[N_ASG];
__device__ int   d_count[E_NUM];

// ===========================================================================
// Helpers
// ===========================================================================
__device__ __forceinline__ uint32_t smem_u32(const void* p) {
    uint32_t a;
    asm("{ .reg .u64 t; cvta.to.shared.u64 t, %1; cvt.u32.u64 %0, t; }" : "=r"(a) : "l"(p));
    return a;
}
__device__ __forceinline__ void ldsm_x4(uint32_t& r0, uint32_t& r1, uint32_t& r2, uint32_t& r3,
                                        uint32_t addr) {
    asm volatile("ldmatrix.sync.aligned.m8n8.x4.shared.b16 {%0,%1,%2,%3}, [%4];"
        : "=r"(r0), "=r"(r1), "=r"(r2), "=r"(r3) : "r"(addr));
}
__device__ __forceinline__ void mma_f16(float* c, uint32_t a0, uint32_t a1, uint32_t a2,
                                        uint32_t a3, uint32_t b0, uint32_t b1) {
    asm volatile("mma.sync.aligned.m16n8k16.row.col.f32.f16.f16.f32 "
        "{%0,%1,%2,%3}, {%4,%5,%6,%7}, {%8,%9}, {%0,%1,%2,%3};"
        : "+f"(c[0]), "+f"(c[1]), "+f"(c[2]), "+f"(c[3])
        : "r"(a0), "r"(a1), "r"(a2), "r"(a3), "r"(b0), "r"(b1));
}
__device__ __forceinline__ void cp16(uint32_t dst, const void* src, int sz) {
    asm volatile("cp.async.cg.shared.global [%0], [%1], 16, %2;"
                 :: "r"(dst), "l"(src), "r"(sz) : "memory");
}
#define CP_COMMIT() asm volatile("cp.async.commit_group;" ::: "memory")
#define CP_WAIT0()  asm volatile("cp.async.wait_group 0;" ::: "memory")

// ===========================================================================
// 0) Pre-convert weights fp32 -> plain fp16 (8 values / thread)
// ===========================================================================
__global__ void conv_h(const float* __restrict__ src, int which, int total)
{
    int idx = blockIdx.x * 256 + threadIdx.x;
    if (idx >= total) return;
    unsigned char* dst = (which == 1) ? w1buf : w2buf;
    const float4* s = reinterpret_cast<const float4*>(src + (size_t)idx * 8);
    float4 v0 = s[0], v1 = s[1];
    __half2 h0 = __floats2half2_rn(v0.x, v0.y);
    __half2 h1 = __floats2half2_rn(v0.z, v0.w);
    __half2 h2 = __floats2half2_rn(v1.x, v1.y);
    __half2 h3 = __floats2half2_rn(v1.z, v1.w);
    *reinterpret_cast<uint4*>(dst + (size_t)idx * 16) = make_uint4(
        *reinterpret_cast<uint32_t*>(&h0), *reinterpret_cast<uint32_t*>(&h1),
        *reinterpret_cast<uint32_t*>(&h2), *reinterpret_cast<uint32_t*>(&h3));
}

// ===========================================================================
// 1) Router: x read ONCE. Warp w handles k-chunk [w*128, w*128+128) for all
//    8 experts; cross-warp reduce in smem. Fused x -> fp16 conversion.
// ===========================================================================
__global__ void router_kernel(const float* __restrict__ x, const float* __restrict__ rw)
{
    int t = blockIdx.x;
    int tid = threadIdx.x;
    int w = tid >> 5;
    int lane = tid & 31;
    const float* xr = x + (size_t)t * H_DIM;

    // single x load per thread (float4 = 4 consecutive)
    float4 xv = reinterpret_cast<const float4*>(xr)[tid];

    // fused conversion into xbuf
    {
        __half2 a = __floats2half2_rn(xv.x, xv.y);
        __half2 b = __floats2half2_rn(xv.z, xv.w);
        unsigned char* d = xbuf + (size_t)t * NK1 * 128 + (tid >> 4) * 128 + (tid & 15) * 8;
        *reinterpret_cast<uint2*>(d) =
            make_uint2(*reinterpret_cast<uint32_t*>(&a), *reinterpret_cast<uint32_t*>(&b));
    }

    // partial dots for all experts over this thread's 4 elements
    __shared__ float part[8][E_NUM];
    float acc[E_NUM];
    #pragma unroll
    for (int e = 0; e < E_NUM; e++) {
        float4 wv = reinterpret_cast<const float4*>(rw + (size_t)e * H_DIM)[tid];
        acc[e] = xv.x * wv.x + xv.y * wv.y + xv.z * wv.z + xv.w * wv.w;
    }
    #pragma unroll
    for (int e = 0; e < E_NUM; e++) {
        #pragma unroll
        for (int o = 16; o > 0; o >>= 1)
            acc[e] += __shfl_xor_sync(0xffffffffu, acc[e], o);
    }
    if (lane < E_NUM) part[w][lane] = acc[lane];   // lane e writes acc[e]? no: all lanes hold all sums
    // note: after full reduce, every lane holds the warp total for each e.
    __syncthreads();

    if (tid == 0) {
        float logits[E_NUM];
        #pragma unroll
        for (int e = 0; e < E_NUM; e++) {
            float s = 0.f;
            #pragma unroll
            for (int ww = 0; ww < 8; ww++) s += part[ww][e];
            logits[e] = s;
        }
        float mx = logits[0];
        #pragma unroll
        for (int e = 1; e < E_NUM; e++) mx = fmaxf(mx, logits[e]);
        float ex[E_NUM]; float s = 0.f;
        #pragma unroll
        for (int e = 0; e < E_NUM; e++) { ex[e] = expf(logits[e] - mx); s += ex[e]; }
        float inv = 1.f / s;
        int i0 = 0;
        #pragma unroll
        for (int e = 1; e < E_NUM; e++) if (ex[e] > ex[i0]) i0 = e;
        int i1 = (i0 == 0) ? 1 : 0;
        #pragma unroll
        for (int e = 0; e < E_NUM; e++) if (e != i0 && ex[e] > ex[i1]) i1 = e;
        d_topi[t * 2 + 0] = i0;  d_topw[t * 2 + 0] = ex[i0] * inv;
        d_topi[t * 2 + 1] = i1;  d_topw[t * 2 + 1] = ex[i1] * inv;
    }
}

// ===========================================================================
// 2) Parallel deterministic per-expert lists (proven R13)
// ===========================================================================
#define CHUNK (N_ASG / 256)          // 32
__global__ void build_lists_kernel()
{
    int e = blockIdx.x;
    int tid = threadIdx.x;
    int lane = tid & 31, w = tid >> 5;

    int base = tid * CHUNK;
    int cnt = 0;
    int local[CHUNK];
    #pragma unroll 8
    for (int j = 0; j < CHUNK; j++) {
        int idx = base + j;
        if (d_topi[idx] == e) local[cnt++] = idx;
    }

    __shared__ int wsum[8];
    int v = cnt;
    #pragma unroll
    for (int o = 1; o < 32; o <<= 1) {
        int n = __shfl_up_sync(0xffffffffu, v, o);
        if (lane >= o) v += n;
    }
    if (lane == 31) wsum[w] = v;
    int excl = v - cnt;
    __syncthreads();
    if (w == 0 && lane < 8) {
        int t = wsum[lane];
        #pragma unroll
        for (int o = 1; o < 8; o <<= 1) {
            int n = __shfl_up_sync(0xffu, t, o);
            if (lane >= o) t += n;
        }
        wsum[lane] = t - wsum[lane];
        if (lane == 7) d_count[e] = t;
    }
    __syncthreads();
    int pos = wsum[w] + excl;
    for (int j = 0; j < cnt; j++)
        d_asg[e * T_TOK + pos + j] = local[j];
}

// ===========================================================================
// cp.async one k64 tile (A+B): 128 threads, thread tid loads A row tid and
// B row tid (8 x 16B chunks each). XOR swizzle chunk ^ (row & 7).
// ===========================================================================
#define ISSUE_SLAB(stage, slab)                                                 \
    {                                                                           \
        uint32_t dA = sbase + (stage) * STAGEB + tid * 128u;                    \
        uint32_t dB = dA + TILEB;                                               \
        const unsigned char* sa = srcA + (size_t)(slab) * 128;                  \
        const unsigned char* sb2 = srcB + (size_t)(slab) * 128;                 \
        _Pragma("unroll")                                                       \
        for (int j = 0; j < 8; j++) {                                           \
            uint32_t so = (uint32_t)((j ^ (tid & 7)) * 16);                     \
            cp16(dA + so, sa + j * 16, szA);                                    \
            cp16(dB + so, sb2 + j * 16, 16);                                    \
        }                                                                       \
    }

// ===========================================================================
// MMA on one k64 tile. Warp tile 64x64: mf 0..3, nf 0..7. kh = k16 chunk.
// ===========================================================================
#define MMA_SLAB(sbb)                                                           \
    _Pragma("unroll")                                                           \
    for (int kh = 0; kh < 4; kh++) {                                            \
        uint32_t ac = (((uint32_t)(kh * 2 + (lane >> 4)) ^ akey) * 16);         \
        uint32_t bc = (((uint32_t)(kh * 2 + ((lane >> 3) & 1)) ^ akey) * 16);   \
        uint32_t sA = (sbb) + arow + ac;                                        \
        uint32_t sB = (sbb) + TILEB + brow + bc;                                \
        uint32_t ah[4][4], bh[8][2];                                            \
        _Pragma("unroll")                                                       \
        for (int mf = 0; mf < 4; mf++)                                          \
            ldsm_x4(ah[mf][0], ah[mf][1], ah[mf][2], ah[mf][3], sA + mf * 2048);\
        _Pragma("unroll")                                                       \
        for (int nb = 0; nb < 4; nb++) {                                        \
            uint32_t t0, t1, t2, t3;                                            \
            ldsm_x4(t0, t1, t2, t3, sB + nb * 2048);                            \
            bh[2*nb][0] = t0; bh[2*nb][1] = t1;                                 \
            bh[2*nb+1][0] = t2; bh[2*nb+1][1] = t3;                             \
        }                                                                       \
        _Pragma("unroll")                                                       \
        for (int mf = 0; mf < 4; mf++)                                          \
            _Pragma("unroll")                                                   \
            for (int nf = 0; nf < 8; nf++)                                      \
                mma_f16(c[mf][nf], ah[mf][0], ah[mf][1], ah[mf][2], ah[mf][3],  \
                        bh[nf][0], bh[nf][1]);                                  \
    }

// ===========================================================================
// 3) GEMM1: h = silu(x Wg^T) * (x Wu^T)    (128 threads, warp 64x64)
// ===========================================================================
__global__ __launch_bounds__(128, 2)
void gemm1_tc()
{
    int e = blockIdx.z;
    int cnt = d_count[e];
    int row0 = blockIdx.y * BM;
    if (row0 >= cnt) return;
    int col0 = blockIdx.x * 64;

    extern __shared__ char sm[];
    __shared__ int toks[BM];
    int tid = threadIdx.x, lane = tid & 31, wid = tid >> 5;

    {
        int r = row0 + tid;
        toks[tid] = (r < cnt) ? d_asg[e * T_TOK + r] : -1;
    }
    __syncthreads();

    int atok = toks[tid];
    bool avalid = (atok >= 0);
    const unsigned char* srcA = avalid ? xbuf + (size_t)(atok >> 1) * NK1 * 128 : xbuf;
    int szA = avalid ? 16 : 0;
    int g = tid >> 3, pr = g >> 1, sub = g & 1;
    int o = col0 + pr * 8 + (tid & 7) + (sub ? I_DIM : 0);
    const unsigned char* srcB = w1buf + ((size_t)e * 2816 + o) * NK1 * 128;

    int wm = wid >> 1, wn = wid & 1;            // 2m x 2n, warp 64x64
    int tg = lane >> 2, ti = lane & 3;
    uint32_t sbase = smem_u32(sm);
    uint32_t akey = (uint32_t)(lane & 7);
    uint32_t arow = (uint32_t)(wm * 64 + (lane & 15)) * 128;
    uint32_t brow = (uint32_t)(wn * 64 + (lane & 7) + ((lane >> 4) & 1) * 8) * 128;

    float c[4][8][4] = {};

    const int NK = NK1;
    ISSUE_SLAB(0, 0); CP_COMMIT();
    for (int i = 0; i < NK; i++) {
        CP_WAIT0();
        __syncthreads();
        int b = i & 1;
        if (i + 1 < NK) { ISSUE_SLAB(b ^ 1, i + 1); }
        CP_COMMIT();
        MMA_SLAB(sbase + b * STAGEB);
    }

    // Epilogue: silu(gate)*up -> hbuf plain fp16
    #pragma unroll
    for (int mf = 0; mf < 4; mf++) {
        #pragma unroll
        for (int h = 0; h < 2; h++) {
            int rloc = wm * 64 + mf * 16 + tg + 8 * h;
            int a = toks[rloc];
            if (a < 0) continue;
            unsigned char* hb = hbuf + (size_t)a * NK2 * 128;
            #pragma unroll
            for (int q = 0; q < 4; q++) {
                float g0 = c[mf][2*q][2*h],   u0 = c[mf][2*q+1][2*h];
                float g1 = c[mf][2*q][2*h+1], u1 = c[mf][2*q+1][2*h+1];
                float v0 = u0 * (g0 / (1.f + __expf(-g0)));
                float v1 = u1 * (g1 / (1.f + __expf(-g1)));
                int hc = col0 + (wn * 4 + q) * 8 + ti * 2;
                int s = hc >> 6, cc = hc & 63;
                __half2 hv = __floats2half2_rn(v0, v1);
                *reinterpret_cast<uint32_t*>(hb + (size_t)s * 128 + cc * 2) =
                    *reinterpret_cast<uint32_t*>(&hv);
            }
        }
    }
}

// ===========================================================================
// 4) GEMM2: y = (h down^T) * weight    (128 threads, warp 64x64)
// ===========================================================================
__global__ __launch_bounds__(128, 2)
void gemm2_tc()
{
    int e = blockIdx.z;
    int cnt = d_count[e];
    int row0 = blockIdx.y * BM;
    if (row0 >= cnt) return;
    int col0 = blockIdx.x * BN;

    extern __shared__ char sm[];
    __shared__ int toks[BM];
    int tid = threadIdx.x, lane = tid & 31, wid = tid >> 5;

    {
        int r = row0 + tid;
        toks[tid] = (r < cnt) ? d_asg[e * T_TOK + r] : -1;
    }
    __syncthreads();

    int atok = toks[tid];
    bool avalid = (atok >= 0);
    const unsigned char* srcA = avalid ? hbuf + (size_t)atok * NK2 * 128 : hbuf;
    int szA = avalid ? 16 : 0;
    const unsigned char* srcB = w2buf + ((size_t)e * 1024 + col0 + tid) * NK2 * 128;

    int wm = wid >> 1, wn = wid & 1;
    int tg = lane >> 2, ti = lane & 3;
    uint32_t sbase = smem_u32(sm);
    uint32_t akey = (uint32_t)(lane & 7);
    uint32_t arow = (uint32_t)(wm * 64 + (lane & 15)) * 128;
    uint32_t brow = (uint32_t)(wn * 64 + (lane & 7) + ((lane >> 4) & 1) * 8) * 128;

    float c[4][8][4] = {};

    const int NK = NK2;
    ISSUE_SLAB(0, 0); CP_COMMIT();
    for (int i = 0; i < NK; i++) {
        CP_WAIT0();
        __syncthreads();
        int b = i & 1;
        if (i + 1 < NK) { ISSUE_SLAB(b ^ 1, i + 1); }
        CP_COMMIT();
        MMA_SLAB(sbase + b * STAGEB);
    }

    #pragma unroll
    for (int mf = 0; mf < 4; mf++) {
        #pragma unroll
        for (int h = 0; h < 2; h++) {
            int rloc = wm * 64 + mf * 16 + tg + 8 * h;
            int a = toks[rloc];
            if (a < 0) continue;
            float wgt = d_topw[a];
            float* dst = d_yslot + (size_t)a * H_DIM;
            #pragma unroll
            for (int nf = 0; nf < 8; nf++) {
                int colc = col0 + wn * 64 + nf * 8 + ti * 2;
                dst[colc]     = c[mf][nf][2*h]   * wgt;
                dst[colc + 1] = c[mf][nf][2*h+1] * wgt;
            }
        }
    }
}

// ===========================================================================
// 5) Combine
// ===========================================================================
__global__ void combine_kernel(float* __restrict__ out)
{
    int i = blockIdx.x * blockDim.x + threadIdx.x;
    int t = i >> 8;
    int h4 = i & 255;
    const float4* y4 = reinterpret_cast<const float4*>(d_yslot);
    float4 a = y4[(size_t)t * 512 + h4];
    float4 b = y4[(size_t)t * 512 + 256 + h4];
    float4 rr;
    rr.x = a.x + b.x; rr.y = a.y + b.y; rr.z = a.z + b.z; rr.w = a.w + b.w;
    reinterpret_cast<float4*>(out)[i] = rr;
}

// ===========================================================================
extern "C" void kernel_launch(void* const* d_in, const int* in_sizes, int n_in,
                              void* d_out, int out_size)
{
    const float* hidden = (const float*)d_in[0];
    const float* rw     = (const float*)d_in[1];
    const float* gup    = (const float*)d_in[2];
    const float* down   = (const float*)d_in[3];
    float* out          = (float*)d_out;

    cudaFuncSetAttribute(gemm1_tc, cudaFuncAttributeMaxDynamicSharedMemorySize, SMEM_BYTES);
    cudaFuncSetAttribute(gemm2_tc, cudaFuncAttributeMaxDynamicSharedMemorySize, SMEM_BYTES);

    {
        int t1 = E_NUM * 2816 * H_DIM / 8;
        conv_h<<<(t1 + 255) / 256, 256>>>(gup, 1, t1);
        int t2 = E_NUM * 1024 * I_DIM / 8;
        conv_h<<<(t2 + 255) / 256, 256>>>(down, 2, t2);
    }

    router_kernel<<<T_TOK, 256>>>(hidden, rw);
    build_lists_kernel<<<E_NUM, 256>>>();

    {
        dim3 grid(I_DIM / 64, T_TOK / BM, E_NUM);    // 22 x 32 x 8
        gemm1_tc<<<grid, 128, SMEM_BYTES>>>();
    }
    {
        dim3 grid(H_DIM / BN, T_TOK / BM, E_NUM);    // 8 x 32 x 8
        gemm2_tc<<<grid, 128, SMEM_BYTES>>>();
    }
    {
        int n4 = T_TOK * H_DIM / 4;
        combine_kernel<<<n4 / 256, 256>>>(out);
    }
}

// round 15
// speedup vs baseline: 1.3819x; 1.3819x over previous
#include <cuda_runtime.h>
#include <cuda_fp16.h>
#include <math.h>
#include <cstdint>

// ===========================================================================
// Problem constants
// ===========================================================================
#define T_TOK   4096
#define H_DIM   1024
#define I_DIM   1408
#define E_NUM   8
#define N_ASG   (T_TOK * 2)
#define NK1     16                  // H_DIM/64 tiles (gemm1 K)
#define NK2     22                  // I_DIM/64 tiles (gemm2 K)

// Tiling: CTA 128x128, 8 warps = 4(m) x 2(n), warp tile 32x64  (R13 proven)
#define BM      128
#define BN      128
#define TILEB   16384               // 128 rows x 128B (64 fp16 k-values)
#define STAGEB  (2 * TILEB)         // A + B = 32768
#define SMEM_BYTES (2 * STAGEB)     // 65536 -> 2 CTAs/SM

// Plain fp16 gmem, row-major K-contiguous: (row, k64-slab) -> 128B block
__device__ __align__(128) unsigned char xbuf[(size_t)T_TOK * NK1 * 128];
__device__ __align__(128) unsigned char w1buf[(size_t)E_NUM * 2816 * NK1 * 128];
__device__ __align__(128) unsigned char w2buf[(size_t)E_NUM * 1024 * NK2 * 128];
__device__ __align__(128) unsigned char hbuf[(size_t)N_ASG * NK2 * 128];
__device__ float d_yslot[(size_t)N_ASG * H_DIM];
__device__ int   d_asg[E_NUM * T_TOK];
__device__ float d_topw[N_ASG];
__device__ int   d_topi[N_ASG];
__device__ int   d_count[E_NUM];

// ===========================================================================
// Helpers
// ===========================================================================
__device__ __forceinline__ uint32_t smem_u32(const void* p) {
    uint32_t a;
    asm("{ .reg .u64 t; cvta.to.shared.u64 t, %1; cvt.u32.u64 %0, t; }" : "=r"(a) : "l"(p));
    return a;
}
__device__ __forceinline__ void ldsm_x4(uint32_t& r0, uint32_t& r1, uint32_t& r2, uint32_t& r3,
                                        uint32_t addr) {
    asm volatile("ldmatrix.sync.aligned.m8n8.x4.shared.b16 {%0,%1,%2,%3}, [%4];"
        : "=r"(r0), "=r"(r1), "=r"(r2), "=r"(r3) : "r"(addr));
}
__device__ __forceinline__ void mma_f16(float* c, uint32_t a0, uint32_t a1, uint32_t a2,
                                        uint32_t a3, uint32_t b0, uint32_t b1) {
    asm volatile("mma.sync.aligned.m16n8k16.row.col.f32.f16.f16.f32 "
        "{%0,%1,%2,%3}, {%4,%5,%6,%7}, {%8,%9}, {%0,%1,%2,%3};"
        : "+f"(c[0]), "+f"(c[1]), "+f"(c[2]), "+f"(c[3])
        : "r"(a0), "r"(a1), "r"(a2), "r"(a3), "r"(b0), "r"(b1));
}
__device__ __forceinline__ void cp16(uint32_t dst, const void* src, int sz) {
    asm volatile("cp.async.cg.shared.global [%0], [%1], 16, %2;"
                 :: "r"(dst), "l"(src), "r"(sz) : "memory");
}
#define CP_COMMIT() asm volatile("cp.async.commit_group;" ::: "memory")
#define CP_WAIT0()  asm volatile("cp.async.wait_group 0;" ::: "memory")

// ===========================================================================
// 0) Pre-convert weights fp32 -> plain fp16 (8 values / thread)
// ===========================================================================
__global__ void conv_h(const float* __restrict__ src, int which, int total)
{
    int idx = blockIdx.x * 256 + threadIdx.x;
    if (idx >= total) return;
    unsigned char* dst = (which == 1) ? w1buf : w2buf;
    const float4* s = reinterpret_cast<const float4*>(src + (size_t)idx * 8);
    float4 v0 = s[0], v1 = s[1];
    __half2 h0 = __floats2half2_rn(v0.x, v0.y);
    __half2 h1 = __floats2half2_rn(v0.z, v0.w);
    __half2 h2 = __floats2half2_rn(v1.x, v1.y);
    __half2 h3 = __floats2half2_rn(v1.z, v1.w);
    *reinterpret_cast<uint4*>(dst + (size_t)idx * 16) = make_uint4(
        *reinterpret_cast<uint32_t*>(&h0), *reinterpret_cast<uint32_t*>(&h1),
        *reinterpret_cast<uint32_t*>(&h2), *reinterpret_cast<uint32_t*>(&h3));
}

// ===========================================================================
// 1) Router (R14 proven): x read ONCE per thread, all 8 expert dots computed
//    from the same registers; cross-warp reduce via smem; fused x->fp16.
// ===========================================================================
__global__ void router_kernel(const float* __restrict__ x, const float* __restrict__ rw)
{
    int t = blockIdx.x;
    int tid = threadIdx.x;
    int w = tid >> 5;
    int lane = tid & 31;
    const float* xr = x + (size_t)t * H_DIM;

    float4 xv = reinterpret_cast<const float4*>(xr)[tid];

    // fused conversion into xbuf
    {
        __half2 a = __floats2half2_rn(xv.x, xv.y);
        __half2 b = __floats2half2_rn(xv.z, xv.w);
        unsigned char* d = xbuf + (size_t)t * NK1 * 128 + (tid >> 4) * 128 + (tid & 15) * 8;
        *reinterpret_cast<uint2*>(d) =
            make_uint2(*reinterpret_cast<uint32_t*>(&a), *reinterpret_cast<uint32_t*>(&b));
    }

    __shared__ float part[8][E_NUM];
    float acc[E_NUM];
    #pragma unroll
    for (int e = 0; e < E_NUM; e++) {
        float4 wv = reinterpret_cast<const float4*>(rw + (size_t)e * H_DIM)[tid];
        acc[e] = xv.x * wv.x + xv.y * wv.y + xv.z * wv.z + xv.w * wv.w;
    }
    #pragma unroll
    for (int e = 0; e < E_NUM; e++) {
        #pragma unroll
        for (int o = 16; o > 0; o >>= 1)
            acc[e] += __shfl_xor_sync(0xffffffffu, acc[e], o);
    }
    if (lane < E_NUM) part[w][lane] = acc[lane];
    __syncthreads();

    if (tid == 0) {
        float logits[E_NUM];
        #pragma unroll
        for (int e = 0; e < E_NUM; e++) {
            float s = 0.f;
            #pragma unroll
            for (int ww = 0; ww < 8; ww++) s += part[ww][e];
            logits[e] = s;
        }
        float mx = logits[0];
        #pragma unroll
        for (int e = 1; e < E_NUM; e++) mx = fmaxf(mx, logits[e]);
        float ex[E_NUM]; float s = 0.f;
        #pragma unroll
        for (int e = 0; e < E_NUM; e++) { ex[e] = expf(logits[e] - mx); s += ex[e]; }
        float inv = 1.f / s;
        int i0 = 0;
        #pragma unroll
        for (int e = 1; e < E_NUM; e++) if (ex[e] > ex[i0]) i0 = e;
        int i1 = (i0 == 0) ? 1 : 0;
        #pragma unroll
        for (int e = 0; e < E_NUM; e++) if (e != i0 && ex[e] > ex[i1]) i1 = e;
        d_topi[t * 2 + 0] = i0;  d_topw[t * 2 + 0] = ex[i0] * inv;
        d_topi[t * 2 + 1] = i1;  d_topw[t * 2 + 1] = ex[i1] * inv;
    }
}

// ===========================================================================
// 2) Parallel deterministic per-expert lists (R13 proven)
// ===========================================================================
#define CHUNK (N_ASG / 256)          // 32
__global__ void build_lists_kernel()
{
    int e = blockIdx.x;
    int tid = threadIdx.x;
    int lane = tid & 31, w = tid >> 5;

    int base = tid * CHUNK;
    int cnt = 0;
    int local[CHUNK];
    #pragma unroll 8
    for (int j = 0; j < CHUNK; j++) {
        int idx = base + j;
        if (d_topi[idx] == e) local[cnt++] = idx;
    }

    __shared__ int wsum[8];
    int v = cnt;
    #pragma unroll
    for (int o = 1; o < 32; o <<= 1) {
        int n = __shfl_up_sync(0xffffffffu, v, o);
        if (lane >= o) v += n;
    }
    if (lane == 31) wsum[w] = v;
    int excl = v - cnt;
    __syncthreads();
    if (w == 0 && lane < 8) {
        int t = wsum[lane];
        #pragma unroll
        for (int o = 1; o < 8; o <<= 1) {
            int n = __shfl_up_sync(0xffu, t, o);
            if (lane >= o) t += n;
        }
        wsum[lane] = t - wsum[lane];
        if (lane == 7) d_count[e] = t;
    }
    __syncthreads();
    int pos = wsum[w] + excl;
    for (int j = 0; j < cnt; j++)
        d_asg[e * T_TOK + pos + j] = local[j];
}

// ===========================================================================
// cp.async one k64 tile (A+B), 4 x 16B chunks each per thread. (R13)
// ===========================================================================
#define ISSUE_SLAB(stage, slab)                                                 \
    {                                                                           \
        uint32_t dA = sbase + (stage) * STAGEB + lr * 128u;                     \
        uint32_t dB = dA + TILEB;                                               \
        const unsigned char* sa = srcA + (size_t)(slab) * 128;                  \
        const unsigned char* sb2 = srcB + (size_t)(slab) * 128;                 \
        _Pragma("unroll")                                                       \
        for (int j = 0; j < 4; j++) {                                           \
            int cch = lh * 4 + j;                                               \
            uint32_t so = (uint32_t)((cch ^ (lr & 7)) * 16);                    \
            cp16(dA + so, sa + cch * 16, szA);                                  \
            cp16(dB + so, sb2 + cch * 16, 16);                                  \
        }                                                                       \
    }

// ===========================================================================
// MMA on one k64 tile. Warp tile 32x64. (R13)
// ===========================================================================
#define MMA_SLAB(sbb)                                                           \
    _Pragma("unroll")                                                           \
    for (int kh = 0; kh < 4; kh++) {                                            \
        uint32_t ac = (((uint32_t)(kh * 2 + (lane >> 4)) ^ akey) * 16);         \
        uint32_t bc = (((uint32_t)(kh * 2 + ((lane >> 3) & 1)) ^ akey) * 16);   \
        uint32_t sA = (sbb) + arow + ac;                                        \
        uint32_t sB = (sbb) + TILEB + brow + bc;                                \
        uint32_t ah[2][4], bh[8][2];                                            \
        _Pragma("unroll")                                                       \
        for (int mf = 0; mf < 2; mf++)                                          \
            ldsm_x4(ah[mf][0], ah[mf][1], ah[mf][2], ah[mf][3], sA + mf * 2048);\
        _Pragma("unroll")                                                       \
        for (int nb = 0; nb < 4; nb++) {                                        \
            uint32_t t0, t1, t2, t3;                                            \
            ldsm_x4(t0, t1, t2, t3, sB + nb * 2048);                            \
            bh[2*nb][0] = t0; bh[2*nb][1] = t1;                                 \
            bh[2*nb+1][0] = t2; bh[2*nb+1][1] = t3;                             \
        }                                                                       \
        _Pragma("unroll")                                                       \
        for (int mf = 0; mf < 2; mf++)                                          \
            _Pragma("unroll")                                                   \
            for (int nf = 0; nf < 8; nf++)                                      \
                mma_f16(c[mf][nf], ah[mf][0], ah[mf][1], ah[mf][2], ah[mf][3],  \
                        bh[nf][0], bh[nf][1]);                                  \
    }

// ===========================================================================
// 3) GEMM1: h = silu(x Wg^T) * (x Wu^T)   (R13 proven config)
// ===========================================================================
__global__ __launch_bounds__(256, 2)
void gemm1_tc()
{
    int e = blockIdx.z;
    int cnt = d_count[e];
    int row0 = blockIdx.y * BM;
    if (row0 >= cnt) return;
    int col0 = blockIdx.x * 64;

    extern __shared__ char sm[];
    __shared__ int toks[BM];
    int tid = threadIdx.x, lane = tid & 31, wid = tid >> 5;

    if (tid < BM) {
        int r = row0 + tid;
        toks[tid] = (r < cnt) ? d_asg[e * T_TOK + r] : -1;
    }
    __syncthreads();

    int lr = tid >> 1, lh = tid & 1;
    int atok = toks[lr];
    bool avalid = (atok >= 0);
    const unsigned char* srcA = avalid ? xbuf + (size_t)(atok >> 1) * NK1 * 128 : xbuf;
    int szA = avalid ? 16 : 0;
    int g = lr >> 3, pr = g >> 1, sub = g & 1;
    int o = col0 + pr * 8 + (lr & 7) + (sub ? I_DIM : 0);
    const unsigned char* srcB = w1buf + ((size_t)e * 2816 + o) * NK1 * 128;

    int wm = wid >> 1, wn = wid & 1;
    int tg = lane >> 2, ti = lane & 3;
    uint32_t sbase = smem_u32(sm);
    uint32_t akey = (uint32_t)(lane & 7);
    uint32_t arow = (uint32_t)(wm * 32 + (lane & 15)) * 128;
    uint32_t brow = (uint32_t)(wn * 64 + (lane & 7) + ((lane >> 4) & 1) * 8) * 128;

    float c[2][8][4] = {};

    const int NK = NK1;
    ISSUE_SLAB(0, 0); CP_COMMIT();
    for (int i = 0; i < NK; i++) {
        CP_WAIT0();
        __syncthreads();
        int b = i & 1;
        if (i + 1 < NK) { ISSUE_SLAB(b ^ 1, i + 1); }
        CP_COMMIT();
        MMA_SLAB(sbase + b * STAGEB);
    }

    #pragma unroll
    for (int mf = 0; mf < 2; mf++) {
        #pragma unroll
        for (int h = 0; h < 2; h++) {
            int rloc = wm * 32 + mf * 16 + tg + 8 * h;
            int a = toks[rloc];
            if (a < 0) continue;
            unsigned char* hb = hbuf + (size_t)a * NK2 * 128;
            #pragma unroll
            for (int q = 0; q < 4; q++) {
                float g0 = c[mf][2*q][2*h],   u0 = c[mf][2*q+1][2*h];
                float g1 = c[mf][2*q][2*h+1], u1 = c[mf][2*q+1][2*h+1];
                float v0 = u0 * (g0 / (1.f + __expf(-g0)));
                float v1 = u1 * (g1 / (1.f + __expf(-g1)));
                int hc = col0 + (wn * 4 + q) * 8 + ti * 2;
                int s = hc >> 6, cc = hc & 63;
                __half2 hv = __floats2half2_rn(v0, v1);
                *reinterpret_cast<uint32_t*>(hb + (size_t)s * 128 + cc * 2) =
                    *reinterpret_cast<uint32_t*>(&hv);
            }
        }
    }
}

// ===========================================================================
// 4) GEMM2: y = (h down^T) * weight   (R13 proven config)
// ===========================================================================
__global__ __launch_bounds__(256, 2)
void gemm2_tc()
{
    int e = blockIdx.z;
    int cnt = d_count[e];
    int row0 = blockIdx.y * BM;
    if (row0 >= cnt) return;
    int col0 = blockIdx.x * BN;

    extern __shared__ char sm[];
    __shared__ int toks[BM];
    int tid = threadIdx.x, lane = tid & 31, wid = tid >> 5;

    if (tid < BM) {
        int r = row0 + tid;
        toks[tid] = (r < cnt) ? d_asg[e * T_TOK + r] : -1;
    }
    __syncthreads();

    int lr = tid >> 1, lh = tid & 1;
    int atok = toks[lr];
    bool avalid = (atok >= 0);
    const unsigned char* srcA = avalid ? hbuf + (size_t)atok * NK2 * 128 : hbuf;
    int szA = avalid ? 16 : 0;
    const unsigned char* srcB = w2buf + ((size_t)e * 1024 + col0 + lr) * NK2 * 128;

    int wm = wid >> 1, wn = wid & 1;
    int tg = lane >> 2, ti = lane & 3;
    uint32_t sbase = smem_u32(sm);
    uint32_t akey = (uint32_t)(lane & 7);
    uint32_t arow = (uint32_t)(wm * 32 + (lane & 15)) * 128;
    uint32_t brow = (uint32_t)(wn * 64 + (lane & 7) + ((lane >> 4) & 1) * 8) * 128;

    float c[2][8][4] = {};

    const int NK = NK2;
    ISSUE_SLAB(0, 0); CP_COMMIT();
    for (int i = 0; i < NK; i++) {
        CP_WAIT0();
        __syncthreads();
        int b = i & 1;
        if (i + 1 < NK) { ISSUE_SLAB(b ^ 1, i + 1); }
        CP_COMMIT();
        MMA_SLAB(sbase + b * STAGEB);
    }

    #pragma unroll
    for (int mf = 0; mf < 2; mf++) {
        #pragma unroll
        for (int h = 0; h < 2; h++) {
            int rloc = wm * 32 + mf * 16 + tg + 8 * h;
            int a = toks[rloc];
            if (a < 0) continue;
            float wgt = d_topw[a];
            float* dst = d_yslot + (size_t)a * H_DIM;
            #pragma unroll
            for (int nf = 0; nf < 8; nf++) {
                int colc = col0 + wn * 64 + nf * 8 + ti * 2;
                dst[colc]     = c[mf][nf][2*h]   * wgt;
                dst[colc + 1] = c[mf][nf][2*h+1] * wgt;
            }
        }
    }
}

// ===========================================================================
// 5) Combine
// ===========================================================================
__global__ void combine_kernel(float* __restrict__ out)
{
    int i = blockIdx.x * blockDim.x + threadIdx.x;
    int t = i >> 8;
    int h4 = i & 255;
    const float4* y4 = reinterpret_cast<const float4*>(d_yslot);
    float4 a = y4[(size_t)t * 512 + h4];
    float4 b = y4[(size_t)t * 512 + 256 + h4];
    float4 rr;
    rr.x = a.x + b.x; rr.y = a.y + b.y; rr.z = a.z + b.z; rr.w = a.w + b.w;
    reinterpret_cast<float4*>(out)[i] = rr;
}

// ===========================================================================
extern "C" void kernel_launch(void* const* d_in, const int* in_sizes, int n_in,
                              void* d_out, int out_size)
{
    const float* hidden = (const float*)d_in[0];
    const float* rw     = (const float*)d_in[1];
    const float* gup    = (const float*)d_in[2];
    const float* down   = (const float*)d_in[3];
    float* out          = (float*)d_out;

    cudaFuncSetAttribute(gemm1_tc, cudaFuncAttributeMaxDynamicSharedMemorySize, SMEM_BYTES);
    cudaFuncSetAttribute(gemm2_tc, cudaFuncAttributeMaxDynamicSharedMemorySize, SMEM_BYTES);

    {
        int t1 = E_NUM * 2816 * H_DIM / 8;
        conv_h<<<(t1 + 255) / 256, 256>>>(gup, 1, t1);
        int t2 = E_NUM * 1024 * I_DIM / 8;
        conv_h<<<(t2 + 255) / 256, 256>>>(down, 2, t2);
    }

    router_kernel<<<T_TOK, 256>>>(hidden, rw);
    build_lists_kernel<<<E_NUM, 256>>>();

    {
        dim3 grid(I_DIM / 64, T_TOK / BM, E_NUM);    // 22 x 32 x 8
        gemm1_tc<<<grid, 256, SMEM_BYTES>>>();
    }
    {
        dim3 grid(H_DIM / BN, T_TOK / BM, E_NUM);    // 8 x 32 x 8
        gemm2_tc<<<grid, 256, SMEM_BYTES>>>();
    }
    {
        int n4 = T_TOK * H_DIM / 4;
        combine_kernel<<<n4 / 256, 256>>>(out);
    }
}

// round 16
// speedup vs baseline: 1.4264x; 1.0322x over previous
#include <cuda_runtime.h>
#include <cuda_fp16.h>
#include <math.h>
#include <cstdint>

// ===========================================================================
// Problem constants
// ===========================================================================
#define T_TOK   4096
#define H_DIM   1024
#define I_DIM   1408
#define E_NUM   8
#define N_ASG   (T_TOK * 2)
#define NK1     16                  // H_DIM/64 tiles (gemm1 K)
#define NK2     22                  // I_DIM/64 tiles (gemm2 K)

// Tiling: CTA 128x128, 8 warps = 4(m) x 2(n), warp tile 32x64  (proven)
#define BM      128
#define BN      128
#define TILEB   16384               // 128 rows x 128B (64 fp16 k-values)
#define STAGEB  (2 * TILEB)         // A + B = 32768
#define SMEM_BYTES (2 * STAGEB)     // 65536 -> 2 CTAs/SM

// Plain fp16 gmem, row-major K-contiguous: (row, k64-slab) -> 128B block
__device__ __align__(128) unsigned char xbuf[(size_t)T_TOK * NK1 * 128];
__device__ __align__(128) unsigned char w1buf[(size_t)E_NUM * 2816 * NK1 * 128];
__device__ __align__(128) unsigned char w2buf[(size_t)E_NUM * 1024 * NK2 * 128];
__device__ __align__(128) unsigned char hbuf[(size_t)N_ASG * NK2 * 128];
__device__ int   d_asg[E_NUM * T_TOK];
__device__ float d_topw[N_ASG];
__device__ int   d_topi[N_ASG];
__device__ int   d_count[E_NUM];

// ===========================================================================
// Helpers
// ===========================================================================
__device__ __forceinline__ uint32_t smem_u32(const void* p) {
    uint32_t a;
    asm("{ .reg .u64 t; cvta.to.shared.u64 t, %1; cvt.u32.u64 %0, t; }" : "=r"(a) : "l"(p));
    return a;
}
__device__ __forceinline__ void ldsm_x4(uint32_t& r0, uint32_t& r1, uint32_t& r2, uint32_t& r3,
                                        uint32_t addr) {
    asm volatile("ldmatrix.sync.aligned.m8n8.x4.shared.b16 {%0,%1,%2,%3}, [%4];"
        : "=r"(r0), "=r"(r1), "=r"(r2), "=r"(r3) : "r"(addr));
}
__device__ __forceinline__ void mma_f16(float* c, uint32_t a0, uint32_t a1, uint32_t a2,
                                        uint32_t a3, uint32_t b0, uint32_t b1) {
    asm volatile("mma.sync.aligned.m16n8k16.row.col.f32.f16.f16.f32 "
        "{%0,%1,%2,%3}, {%4,%5,%6,%7}, {%8,%9}, {%0,%1,%2,%3};"
        : "+f"(c[0]), "+f"(c[1]), "+f"(c[2]), "+f"(c[3])
        : "r"(a0), "r"(a1), "r"(a2), "r"(a3), "r"(b0), "r"(b1));
}
__device__ __forceinline__ void cp16(uint32_t dst, const void* src, int sz) {
    asm volatile("cp.async.cg.shared.global [%0], [%1], 16, %2;"
                 :: "r"(dst), "l"(src), "r"(sz) : "memory");
}
#define CP_COMMIT() asm volatile("cp.async.commit_group;" ::: "memory")
#define CP_WAIT0()  asm volatile("cp.async.wait_group 0;" ::: "memory")

// ===========================================================================
// 0) Pre-convert both weight tensors fp32 -> fp16 in ONE kernel
// ===========================================================================
#define W1_TOTAL (E_NUM * 2816 * H_DIM / 8)
#define W2_TOTAL (E_NUM * 1024 * I_DIM / 8)
__global__ void conv_w(const float* __restrict__ gup, const float* __restrict__ down)
{
    int idx = blockIdx.x * 256 + threadIdx.x;
    const float* src;
    unsigned char* dst;
    int i;
    if (idx < W1_TOTAL) { src = gup;  dst = w1buf; i = idx; }
    else {
        i = idx - W1_TOTAL;
        if (i >= W2_TOTAL) return;
        src = down; dst = w2buf;
    }
    const float4* s = reinterpret_cast<const float4*>(src + (size_t)i * 8);
    float4 v0 = s[0], v1 = s[1];
    __half2 h0 = __floats2half2_rn(v0.x, v0.y);
    __half2 h1 = __floats2half2_rn(v0.z, v0.w);
    __half2 h2 = __floats2half2_rn(v1.x, v1.y);
    __half2 h3 = __floats2half2_rn(v1.z, v1.w);
    *reinterpret_cast<uint4*>(dst + (size_t)i * 16) = make_uint4(
        *reinterpret_cast<uint32_t*>(&h0), *reinterpret_cast<uint32_t*>(&h1),
        *reinterpret_cast<uint32_t*>(&h2), *reinterpret_cast<uint32_t*>(&h3));
}

// ===========================================================================
// 1) Router: x read once; all 8 expert dots from registers; fused x->fp16
// ===========================================================================
__global__ void router_kernel(const float* __restrict__ x, const float* __restrict__ rw)
{
    int t = blockIdx.x;
    int tid = threadIdx.x;
    int w = tid >> 5;
    int lane = tid & 31;
    const float* xr = x + (size_t)t * H_DIM;

    float4 xv = reinterpret_cast<const float4*>(xr)[tid];

    {
        __half2 a = __floats2half2_rn(xv.x, xv.y);
        __half2 b = __floats2half2_rn(xv.z, xv.w);
        unsigned char* d = xbuf + (size_t)t * NK1 * 128 + (tid >> 4) * 128 + (tid & 15) * 8;
        *reinterpret_cast<uint2*>(d) =
            make_uint2(*reinterpret_cast<uint32_t*>(&a), *reinterpret_cast<uint32_t*>(&b));
    }

    __shared__ float part[8][E_NUM];
    float acc[E_NUM];
    #pragma unroll
    for (int e = 0; e < E_NUM; e++) {
        float4 wv = reinterpret_cast<const float4*>(rw + (size_t)e * H_DIM)[tid];
        acc[e] = xv.x * wv.x + xv.y * wv.y + xv.z * wv.z + xv.w * wv.w;
    }
    #pragma unroll
    for (int e = 0; e < E_NUM; e++) {
        #pragma unroll
        for (int o = 16; o > 0; o >>= 1)
            acc[e] += __shfl_xor_sync(0xffffffffu, acc[e], o);
    }
    if (lane < E_NUM) part[w][lane] = acc[lane];
    __syncthreads();

    if (tid == 0) {
        float logits[E_NUM];
        #pragma unroll
        for (int e = 0; e < E_NUM; e++) {
            float s = 0.f;
            #pragma unroll
            for (int ww = 0; ww < 8; ww++) s += part[ww][e];
            logits[e] = s;
        }
        float mx = logits[0];
        #pragma unroll
        for (int e = 1; e < E_NUM; e++) mx = fmaxf(mx, logits[e]);
        float ex[E_NUM]; float s = 0.f;
        #pragma unroll
        for (int e = 0; e < E_NUM; e++) { ex[e] = expf(logits[e] - mx); s += ex[e]; }
        float inv = 1.f / s;
        int i0 = 0;
        #pragma unroll
        for (int e = 1; e < E_NUM; e++) if (ex[e] > ex[i0]) i0 = e;
        int i1 = (i0 == 0) ? 1 : 0;
        #pragma unroll
        for (int e = 0; e < E_NUM; e++) if (e != i0 && ex[e] > ex[i1]) i1 = e;
        d_topi[t * 2 + 0] = i0;  d_topw[t * 2 + 0] = ex[i0] * inv;
        d_topi[t * 2 + 1] = i1;  d_topw[t * 2 + 1] = ex[i1] * inv;
    }
}

// ===========================================================================
// 2) Parallel deterministic per-expert lists
// ===========================================================================
#define CHUNK (N_ASG / 256)          // 32
__global__ void build_lists_kernel()
{
    int e = blockIdx.x;
    int tid = threadIdx.x;
    int lane = tid & 31, w = tid >> 5;

    int base = tid * CHUNK;
    int cnt = 0;
    int local[CHUNK];
    #pragma unroll 8
    for (int j = 0; j < CHUNK; j++) {
        int idx = base + j;
        if (d_topi[idx] == e) local[cnt++] = idx;
    }

    __shared__ int wsum[8];
    int v = cnt;
    #pragma unroll
    for (int o = 1; o < 32; o <<= 1) {
        int n = __shfl_up_sync(0xffffffffu, v, o);
        if (lane >= o) v += n;
    }
    if (lane == 31) wsum[w] = v;
    int excl = v - cnt;
    __syncthreads();
    if (w == 0 && lane < 8) {
        int t = wsum[lane];
        #pragma unroll
        for (int o = 1; o < 8; o <<= 1) {
            int n = __shfl_up_sync(0xffu, t, o);
            if (lane >= o) t += n;
        }
        wsum[lane] = t - wsum[lane];
        if (lane == 7) d_count[e] = t;
    }
    __syncthreads();
    int pos = wsum[w] + excl;
    for (int j = 0; j < cnt; j++)
        d_asg[e * T_TOK + pos + j] = local[j];
}

// ===========================================================================
// cp.async one k64 tile (A+B), 4 x 16B chunks each per thread.
// ===========================================================================
#define ISSUE_SLAB(stage, slab)                                                 \
    {                                                                           \
        uint32_t dA = sbase + (stage) * STAGEB + lr * 128u;                     \
        uint32_t dB = dA + TILEB;                                               \
        const unsigned char* sa = srcA + (size_t)(slab) * 128;                  \
        const unsigned char* sb2 = srcB + (size_t)(slab) * 128;                 \
        _Pragma("unroll")                                                       \
        for (int j = 0; j < 4; j++) {                                           \
            int cch = lh * 4 + j;                                               \
            uint32_t so = (uint32_t)((cch ^ (lr & 7)) * 16);                    \
            cp16(dA + so, sa + cch * 16, szA);                                  \
            cp16(dB + so, sb2 + cch * 16, 16);                                  \
        }                                                                       \
    }

// ===========================================================================
// MMA on one k64 tile. Warp tile 32x64.
// ===========================================================================
#define MMA_SLAB(sbb)                                                           \
    _Pragma("unroll")                                                           \
    for (int kh = 0; kh < 4; kh++) {                                            \
        uint32_t ac = (((uint32_t)(kh * 2 + (lane >> 4)) ^ akey) * 16);         \
        uint32_t bc = (((uint32_t)(kh * 2 + ((lane >> 3) & 1)) ^ akey) * 16);   \
        uint32_t sA = (sbb) + arow + ac;                                        \
        uint32_t sB = (sbb) + TILEB + brow + bc;                                \
        uint32_t ah[2][4], bh[8][2];                                            \
        _Pragma("unroll")                                                       \
        for (int mf = 0; mf < 2; mf++)                                          \
            ldsm_x4(ah[mf][0], ah[mf][1], ah[mf][2], ah[mf][3], sA + mf * 2048);\
        _Pragma("unroll")                                                       \
        for (int nb = 0; nb < 4; nb++) {                                        \
            uint32_t t0, t1, t2, t3;                                            \
            ldsm_x4(t0, t1, t2, t3, sB + nb * 2048);                            \
            bh[2*nb][0] = t0; bh[2*nb][1] = t1;                                 \
            bh[2*nb+1][0] = t2; bh[2*nb+1][1] = t3;                             \
        }                                                                       \
        _Pragma("unroll")                                                       \
        for (int mf = 0; mf < 2; mf++)                                          \
            _Pragma("unroll")                                                   \
            for (int nf = 0; nf < 8; nf++)                                      \
                mma_f16(c[mf][nf], ah[mf][0], ah[mf][1], ah[mf][2], ah[mf][3],  \
                        bh[nf][0], bh[nf][1]);                                  \
    }

// ===========================================================================
// 3) GEMM1: h = silu(x Wg^T) * (x Wu^T)
// ===========================================================================
__global__ __launch_bounds__(256, 2)
void gemm1_tc()
{
    int e = blockIdx.z;
    int cnt = d_count[e];
    int row0 = blockIdx.y * BM;
    if (row0 >= cnt) return;
    int col0 = blockIdx.x * 64;

    extern __shared__ char sm[];
    __shared__ int toks[BM];
    int tid = threadIdx.x, lane = tid & 31, wid = tid >> 5;

    if (tid < BM) {
        int r = row0 + tid;
        toks[tid] = (r < cnt) ? d_asg[e * T_TOK + r] : -1;
    }
    __syncthreads();

    int lr = tid >> 1, lh = tid & 1;
    int atok = toks[lr];
    bool avalid = (atok >= 0);
    const unsigned char* srcA = avalid ? xbuf + (size_t)(atok >> 1) * NK1 * 128 : xbuf;
    int szA = avalid ? 16 : 0;
    int g = lr >> 3, pr = g >> 1, sub = g & 1;
    int o = col0 + pr * 8 + (lr & 7) + (sub ? I_DIM : 0);
    const unsigned char* srcB = w1buf + ((size_t)e * 2816 + o) * NK1 * 128;

    int wm = wid >> 1, wn = wid & 1;
    int tg = lane >> 2, ti = lane & 3;
    uint32_t sbase = smem_u32(sm);
    uint32_t akey = (uint32_t)(lane & 7);
    uint32_t arow = (uint32_t)(wm * 32 + (lane & 15)) * 128;
    uint32_t brow = (uint32_t)(wn * 64 + (lane & 7) + ((lane >> 4) & 1) * 8) * 128;

    float c[2][8][4] = {};

    const int NK = NK1;
    ISSUE_SLAB(0, 0); CP_COMMIT();
    for (int i = 0; i < NK; i++) {
        CP_WAIT0();
        __syncthreads();
        int b = i & 1;
        if (i + 1 < NK) { ISSUE_SLAB(b ^ 1, i + 1); }
        CP_COMMIT();
        MMA_SLAB(sbase + b * STAGEB);
    }

    #pragma unroll
    for (int mf = 0; mf < 2; mf++) {
        #pragma unroll
        for (int h = 0; h < 2; h++) {
            int rloc = wm * 32 + mf * 16 + tg + 8 * h;
            int a = toks[rloc];
            if (a < 0) continue;
            unsigned char* hb = hbuf + (size_t)a * NK2 * 128;
            #pragma unroll
            for (int q = 0; q < 4; q++) {
                float g0 = c[mf][2*q][2*h],   u0 = c[mf][2*q+1][2*h];
                float g1 = c[mf][2*q][2*h+1], u1 = c[mf][2*q+1][2*h+1];
                float v0 = u0 * (g0 / (1.f + __expf(-g0)));
                float v1 = u1 * (g1 / (1.f + __expf(-g1)));
                int hc = col0 + (wn * 4 + q) * 8 + ti * 2;
                int s = hc >> 6, cc = hc & 63;
                __half2 hv = __floats2half2_rn(v0, v1);
                *reinterpret_cast<uint32_t*>(hb + (size_t)s * 128 + cc * 2) =
                    *reinterpret_cast<uint32_t*>(&hv);
            }
        }
    }
}

// ===========================================================================
// 4) GEMM2: out[t] += (h down^T) * weight  via RED.ADD (exactly 2 adds/elem,
//    commutative -> deterministic). d_out zero-initialized by memset.
// ===========================================================================
__global__ __launch_bounds__(256, 2)
void gemm2_tc(float* __restrict__ out)
{
    int e = blockIdx.z;
    int cnt = d_count[e];
    int row0 = blockIdx.y * BM;
    if (row0 >= cnt) return;
    int col0 = blockIdx.x * BN;

    extern __shared__ char sm[];
    __shared__ int toks[BM];
    int tid = threadIdx.x, lane = tid & 31, wid = tid >> 5;

    if (tid < BM) {
        int r = row0 + tid;
        toks[tid] = (r < cnt) ? d_asg[e * T_TOK + r] : -1;
    }
    __syncthreads();

    int lr = tid >> 1, lh = tid & 1;
    int atok = toks[lr];
    bool avalid = (atok >= 0);
    const unsigned char* srcA = avalid ? hbuf + (size_t)atok * NK2 * 128 : hbuf;
    int szA = avalid ? 16 : 0;
    const unsigned char* srcB = w2buf + ((size_t)e * 1024 + col0 + lr) * NK2 * 128;

    int wm = wid >> 1, wn = wid & 1;
    int tg = lane >> 2, ti = lane & 3;
    uint32_t sbase = smem_u32(sm);
    uint32_t akey = (uint32_t)(lane & 7);
    uint32_t arow = (uint32_t)(wm * 32 + (lane & 15)) * 128;
    uint32_t brow = (uint32_t)(wn * 64 + (lane & 7) + ((lane >> 4) & 1) * 8) * 128;

    float c[2][8][4] = {};

    const int NK = NK2;
    ISSUE_SLAB(0, 0); CP_COMMIT();
    for (int i = 0; i < NK; i++) {
        CP_WAIT0();
        __syncthreads();
        int b = i & 1;
        if (i + 1 < NK) { ISSUE_SLAB(b ^ 1, i + 1); }
        CP_COMMIT();
        MMA_SLAB(sbase + b * STAGEB);
    }

    #pragma unroll
    for (int mf = 0; mf < 2; mf++) {
        #pragma unroll
        for (int h = 0; h < 2; h++) {
            int rloc = wm * 32 + mf * 16 + tg + 8 * h;
            int a = toks[rloc];
            if (a < 0) continue;
            float wgt = d_topw[a];
            float* dst = out + (size_t)(a >> 1) * H_DIM;    // token row
            #pragma unroll
            for (int nf = 0; nf < 8; nf++) {
                int colc = col0 + wn * 64 + nf * 8 + ti * 2;
                atomicAdd(dst + colc,     c[mf][nf][2*h]   * wgt);
                atomicAdd(dst + colc + 1, c[mf][nf][2*h+1] * wgt);
            }
        }
    }
}

// ===========================================================================
extern "C" void kernel_launch(void* const* d_in, const int* in_sizes, int n_in,
                              void* d_out, int out_size)
{
    const float* hidden = (const float*)d_in[0];
    const float* rw     = (const float*)d_in[1];
    const float* gup    = (const float*)d_in[2];
    const float* down   = (const float*)d_in[3];
    float* out          = (float*)d_out;

    cudaFuncSetAttribute(gemm1_tc, cudaFuncAttributeMaxDynamicSharedMemorySize, SMEM_BYTES);
    cudaFuncSetAttribute(gemm2_tc, cudaFuncAttributeMaxDynamicSharedMemorySize, SMEM_BYTES);

    // zero-init output (accumulated via RED.ADD in gemm2)
    cudaMemsetAsync(out, 0, (size_t)out_size * sizeof(float));

    {
        int total = W1_TOTAL + W2_TOTAL;
        conv_w<<<(total + 255) / 256, 256>>>(gup, down);
    }

    router_kernel<<<T_TOK, 256>>>(hidden, rw);
    build_lists_kernel<<<E_NUM, 256>>>();

    {
        dim3 grid(I_DIM / 64, T_TOK / BM, E_NUM);    // 22 x 32 x 8
        gemm1_tc<<<grid, 256, SMEM_BYTES>>>();
    }
    {
        dim3 grid(H_DIM / BN, T_TOK / BM, E_NUM);    // 8 x 32 x 8
        gemm2_tc<<<grid, 256, SMEM_BYTES>>>(out);
    }
}